// round 1
// baseline (speedup 1.0000x reference)
#include <cuda_runtime.h>
#include <cstdint>

// ---------------- problem constants ----------------
#define SPATIAL   3136                 // 56*56
#define TOTAL_N   100352               // 32*3136
#define BM        64                   // rows per CTA (3136 % 64 == 0 -> tile never straddles batch)
#define BK        16
#define NCTA      (TOTAL_N / BM)       // 1568
#define BSTRIDE   516                  // padded B smem row stride (floats)
#define TSTRIDE   520                  // padded t' smem row stride (floats)
#define SSTRIDE   65                   // padded s-stage row stride (floats)
#define SMEM_FLOATS (BM * TSTRIDE + 256 * SSTRIDE)   // 33280 + 16640 = 49920
#define SMEM_BYTES  (SMEM_FLOATS * 4)                // 199680
#define TOTAL_OUT (32 * 512 * SPATIAL) // 51380224

// ---------------- scratch (no allocations allowed) ----------------
__device__ float g_sT[256u * 100352u];     // s channel-major [256][N]
__device__ float g_part[512 * NCTA];       // rows 0..255 sums, 256..511 sumsq
__device__ float g_scale[512];
__device__ float g_shift[512];

// ---------------- f32x2 helpers ----------------
union F4U { float4 v; unsigned long long u[2]; float f[4]; };

__device__ __forceinline__ unsigned long long pack2(float lo, float hi) {
    unsigned long long r;
    asm("mov.b64 %0, {%1, %2};" : "=l"(r) : "f"(lo), "f"(hi));
    return r;
}
__device__ __forceinline__ void unpack2(unsigned long long v, float& lo, float& hi) {
    asm("mov.b64 {%0, %1}, %2;" : "=f"(lo), "=f"(hi) : "l"(v));
}
__device__ __forceinline__ void fma2(unsigned long long& d, unsigned long long a, unsigned long long b) {
    asm("fma.rn.f32x2 %0, %1, %2, %3;" : "=l"(d) : "l"(a), "l"(b), "l"(d));
}
__device__ __forceinline__ void add2(unsigned long long& d, unsigned long long a) {
    asm("add.rn.f32x2 %0, %1, %2;" : "=l"(d) : "l"(a), "l"(d));
}

// =====================================================================
// K1: fused GEMM(+residual+bias) -> bilinear -> tanh -> s write + BN partials
// grid = 1568, block = 512, dyn smem = 199680 B
// =====================================================================
__global__ void __launch_bounds__(512, 1)
k1_gemm_bilinear(const float* __restrict__ x,
                 const float* __restrict__ fcw,
                 const float* __restrict__ fcb)
{
    extern __shared__ float sm[];
    float* As  = sm;                       // [BK][BM]    (1024 floats)
    float* Bs  = sm + BK * BM;             // [BK][BSTRIDE] (8256 floats)
    float* ts  = sm;                       // alias: t' tile [64][TSTRIDE]
    float* sst = sm + BM * TSTRIDE;        // s stage [256][SSTRIDE]

    const int tid = threadIdx.x;
    const int tx  = tid & 63;              // col-group owner (0..63)
    const int ty  = tid >> 6;              // row-group owner (0..7)
    const int cta = blockIdx.x;
    const int n0  = cta * BM;
    const int b   = n0 / SPATIAL;
    const int s0  = n0 - b * SPATIAL;
    const float* xb = x + (size_t)b * (512 * SPATIAL);

    // loader coords
    const int ak = tid >> 6;               // 0..7  (k for A tile, two passes)
    const int am = tid & 63;               // m
    const int bk = tid & 15;               // k for B tile
    const int bj = tid >> 4;               // 0..31 (j base)

    unsigned long long acc[8][4];
    #pragma unroll
    for (int i = 0; i < 8; ++i)
        #pragma unroll
        for (int j = 0; j < 4; ++j) acc[i][j] = 0ull;

    // ---- preload tile 0 ----
    float pa0 = xb[ak * SPATIAL + s0 + am];
    float pa1 = xb[(ak + 8) * SPATIAL + s0 + am];
    float pb[16];
    #pragma unroll
    for (int i = 0; i < 16; ++i) pb[i] = fcw[(i * 32 + bj) * 512 + bk];
    As[ak * 64 + am] = pa0;
    As[(ak + 8) * 64 + am] = pa1;
    #pragma unroll
    for (int i = 0; i < 16; ++i) Bs[bk * BSTRIDE + i * 32 + bj] = pb[i];
    __syncthreads();

    const int rt1 = tx >> 2;               // k-tile containing this thread's col group 1
    const int rkb = (tx & 3) * 4;          // col offset inside that tile

    for (int kt = 0; kt < 32; ++kt) {
        // prefetch next tile into registers
        if (kt < 31) {
            const int c0n = (kt + 1) * 16;
            pa0 = xb[(c0n + ak) * SPATIAL + s0 + am];
            pa1 = xb[(c0n + ak + 8) * SPATIAL + s0 + am];
            #pragma unroll
            for (int i = 0; i < 16; ++i)
                pb[i] = fcw[(i * 32 + bj) * 512 + c0n + bk];
        }
        // compute on current smem tile
        #pragma unroll
        for (int k = 0; k < BK; ++k) {
            F4U a0, a1, b0, b1;
            a0.v = *(const float4*)(As + k * 64 + ty * 8);
            a1.v = *(const float4*)(As + k * 64 + ty * 8 + 4);
            b0.v = *(const float4*)(Bs + k * BSTRIDE + tx * 4);
            b1.v = *(const float4*)(Bs + k * BSTRIDE + tx * 4 + 256);
            #pragma unroll
            for (int i = 0; i < 8; ++i) {
                const float av = (i < 4) ? a0.f[i] : a1.f[i - 4];
                unsigned long long ap = pack2(av, av);
                fma2(acc[i][0], ap, b0.u[0]);
                fma2(acc[i][1], ap, b0.u[1]);
                fma2(acc[i][2], ap, b1.u[0]);
                fma2(acc[i][3], ap, b1.u[1]);
            }
        }
        // fold in the residual t (read straight from the A smem tile)
        if (kt == rt1) {
            #pragma unroll
            for (int i = 0; i < 8; ++i) {
                const int row = ty * 8 + i;
                add2(acc[i][0], pack2(As[(rkb + 0) * 64 + row], As[(rkb + 1) * 64 + row]));
                add2(acc[i][1], pack2(As[(rkb + 2) * 64 + row], As[(rkb + 3) * 64 + row]));
            }
        }
        if (kt == rt1 + 16) {
            #pragma unroll
            for (int i = 0; i < 8; ++i) {
                const int row = ty * 8 + i;
                add2(acc[i][2], pack2(As[(rkb + 0) * 64 + row], As[(rkb + 1) * 64 + row]));
                add2(acc[i][3], pack2(As[(rkb + 2) * 64 + row], As[(rkb + 3) * 64 + row]));
            }
        }
        __syncthreads();
        if (kt < 31) {
            As[ak * 64 + am] = pa0;
            As[(ak + 8) * 64 + am] = pa1;
            #pragma unroll
            for (int i = 0; i < 16; ++i) Bs[bk * BSTRIDE + i * 32 + bj] = pb[i];
            __syncthreads();
        }
    }

    // ---- epilogue: t' = acc (+fc_b) into smem (aliases GEMM tiles, all reads done) ----
    float fb[8];
    #pragma unroll
    for (int j = 0; j < 4; ++j) {
        fb[j]     = fcb[tx * 4 + j];
        fb[4 + j] = fcb[256 + tx * 4 + j];
    }
    #pragma unroll
    for (int i = 0; i < 8; ++i) {
        const int row = ty * 8 + i;
        float lo, hi;
        unpack2(acc[i][0], lo, hi);
        ts[row * TSTRIDE + tx * 4 + 0] = lo + fb[0];
        ts[row * TSTRIDE + tx * 4 + 1] = hi + fb[1];
        unpack2(acc[i][1], lo, hi);
        ts[row * TSTRIDE + tx * 4 + 2] = lo + fb[2];
        ts[row * TSTRIDE + tx * 4 + 3] = hi + fb[3];
        unpack2(acc[i][2], lo, hi);
        ts[row * TSTRIDE + 256 + tx * 4 + 0] = lo + fb[4];
        ts[row * TSTRIDE + 256 + tx * 4 + 1] = hi + fb[5];
        unpack2(acc[i][3], lo, hi);
        ts[row * TSTRIDE + 256 + tx * 4 + 2] = lo + fb[6];
        ts[row * TSTRIDE + 256 + tx * 4 + 3] = hi + fb[7];
    }
    __syncthreads();

    // ---- bilinear: s[p][q] = sum_g t[g*16+p] * t[g*16+q], then tanh(/32) ----
    {
        const int r  = tid >> 3;           // row 0..63
        const int pp = tid & 7;
        const float* trow = ts + r * TSTRIDE;
        #pragma unroll
        for (int half = 0; half < 2; ++half) {
            const int p = pp + 8 * half;
            float tr[32];
            #pragma unroll
            for (int g = 0; g < 32; ++g) tr[g] = trow[g * 16 + p];
            unsigned long long sacc[8];
            #pragma unroll
            for (int e = 0; e < 8; ++e) sacc[e] = 0ull;
            #pragma unroll
            for (int g = 0; g < 32; ++g) {
                F4U q0, q1, q2, q3;
                q0.v = *(const float4*)(trow + g * 16);
                q1.v = *(const float4*)(trow + g * 16 + 4);
                q2.v = *(const float4*)(trow + g * 16 + 8);
                q3.v = *(const float4*)(trow + g * 16 + 12);
                unsigned long long tp = pack2(tr[g], tr[g]);
                fma2(sacc[0], tp, q0.u[0]); fma2(sacc[1], tp, q0.u[1]);
                fma2(sacc[2], tp, q1.u[0]); fma2(sacc[3], tp, q1.u[1]);
                fma2(sacc[4], tp, q2.u[0]); fma2(sacc[5], tp, q2.u[1]);
                fma2(sacc[6], tp, q3.u[0]); fma2(sacc[7], tp, q3.u[1]);
            }
            #pragma unroll
            for (int e = 0; e < 8; ++e) {
                float lo, hi;
                unpack2(sacc[e], lo, hi);
                const int q = 2 * e;
                sst[(p * 16 + q)     * SSTRIDE + r] = tanhf(lo * 0.03125f);
                sst[(p * 16 + q + 1) * SSTRIDE + r] = tanhf(hi * 0.03125f);
            }
        }
    }
    __syncthreads();

    // ---- BN partial sums per channel (deterministic, no atomics) ----
    if (tid < 256) {
        float s = 0.f, q = 0.f;
        #pragma unroll 8
        for (int m = 0; m < BM; ++m) {
            const float v = sst[tid * SSTRIDE + m];
            s += v; q += v * v;
        }
        g_part[tid * NCTA + cta]         = s;
        g_part[(tid + 256) * NCTA + cta] = q;
    }
    // ---- coalesced channel-major s write ----
    #pragma unroll
    for (int it = 0; it < 32; ++it) {
        const int idx = it * 512 + tid;
        const int ch  = idx >> 6;
        const int m   = idx & 63;
        g_sT[(size_t)ch * TOTAL_N + n0 + m] = sst[ch * SSTRIDE + m];
    }
}

// =====================================================================
// K2: fold BN stats -> per-channel scale/shift (fp64 reduction)
// grid = 512 blocks (one per output channel c), 256 threads
// =====================================================================
__global__ void k2_stats(const float* __restrict__ gamma,
                         const float* __restrict__ beta)
{
    __shared__ double rs[256], rq[256];
    const int c   = blockIdx.x;
    const int c2  = c >> 1;                 // nearest-interp channel map
    const int tid = threadIdx.x;
    double s = 0.0, q = 0.0;
    for (int i = tid; i < NCTA; i += 256) {
        s += (double)g_part[c2 * NCTA + i];
        q += (double)g_part[(c2 + 256) * NCTA + i];
    }
    rs[tid] = s; rq[tid] = q;
    __syncthreads();
    for (int off = 128; off > 0; off >>= 1) {
        if (tid < off) { rs[tid] += rs[tid + off]; rq[tid] += rq[tid + off]; }
        __syncthreads();
    }
    if (tid == 0) {
        const double inv_n = 1.0 / (double)TOTAL_N;
        const double mean  = rs[0] * inv_n;
        const double var   = rq[0] * inv_n - mean * mean;   // biased var
        const double rstd  = 1.0 / sqrt(var + 1e-5);
        const double g     = (double)gamma[c];
        g_scale[c] = (float)(g * rstd);
        g_shift[c] = (float)((double)beta[c] - mean * rstd * g);
    }
}

// =====================================================================
// K3: out = x + s[c>>1]*scale[c] + shift[c]
// =====================================================================
__global__ void k3_out(const float* __restrict__ x, float* __restrict__ out)
{
    const int idx = blockIdx.x * 256 + threadIdx.x;
    if (idx >= TOTAL_OUT) return;
    const int sp = idx % SPATIAL;
    const int bc = idx / SPATIAL;
    const int c  = bc & 511;
    const int b  = bc >> 9;
    const float sv = g_sT[(size_t)(c >> 1) * TOTAL_N + b * SPATIAL + sp];
    out[idx] = x[idx] + fmaf(sv, g_scale[c], g_shift[c]);
}

// =====================================================================
extern "C" void kernel_launch(void* const* d_in, const int* in_sizes, int n_in,
                              void* d_out, int out_size)
{
    const float* x     = (const float*)d_in[0];
    const float* fcw   = (const float*)d_in[1];
    const float* fcb   = (const float*)d_in[2];
    const float* gamma = (const float*)d_in[3];
    const float* beta  = (const float*)d_in[4];
    float* out = (float*)d_out;

    cudaFuncSetAttribute(k1_gemm_bilinear,
                         cudaFuncAttributeMaxDynamicSharedMemorySize, SMEM_BYTES);

    k1_gemm_bilinear<<<NCTA, 512, SMEM_BYTES>>>(x, fcw, fcb);
    k2_stats<<<512, 256>>>(gamma, beta);
    k3_out<<<(TOTAL_OUT + 255) / 256, 256>>>(x, out);
}

// round 3
// speedup vs baseline: 2.3025x; 2.3025x over previous
#include <cuda_runtime.h>
#include <cstdint>

// ---------------- problem constants ----------------
#define SPATIAL   3136
#define TOTAL_N   100352
#define BM        64
#define NCTA      1568                // TOTAL_N / BM
#define KC        32
#define NSTG      16                  // 512 / 32
#define ASTRIDE   34                  // padded floats per A smem row
#define BSTR      34                  // padded floats per B smem row
#define ABYTES    (64 * ASTRIDE * 4)      // 8704
#define BBYTES    (512 * BSTR * 4)        // 69632
#define STAGEB    (ABYTES + BBYTES)       // 78336
#define TS_STRIDE 520
#define SST_OFF   133120              // 64*520*4
#define SST_STR   68
#define BIAS_OFF  202752              // SST_OFF + 256*68*4
#define SMEM_BYTES 204800
#define TOTAL_OUT (32 * 512 * SPATIAL)

// ---------------- device scratch ----------------
__device__ float g_wp[512 * 512];          // (W + I), tf32-rounded, k-interleaved per 32-chunk
__device__ float g_sT[256u * 100352u];     // s channel-major [256][N]
__device__ float g_part[512 * NCTA];
__device__ float g_scale[512];
__device__ float g_shift[512];

// ---------------- helpers ----------------
union F4U { float4 v; unsigned long long u[2]; float f[4]; };

__device__ __forceinline__ uint32_t smem_u32(const void* p) {
    uint32_t a;
    asm("{ .reg .u64 t; cvta.to.shared.u64 t, %1; cvt.u32.u64 %0, t; }" : "=r"(a) : "l"(p));
    return a;
}
__device__ __forceinline__ void cp4(uint32_t dst, const void* src) {
    asm volatile("cp.async.ca.shared.global [%0], [%1], 4;" :: "r"(dst), "l"(src));
}
__device__ __forceinline__ void cp8(uint32_t dst, const void* src) {
    asm volatile("cp.async.ca.shared.global [%0], [%1], 8;" :: "r"(dst), "l"(src));
}
#define CP_COMMIT() asm volatile("cp.async.commit_group;" ::: "memory")
#define CP_WAIT1()  asm volatile("cp.async.wait_group 1;" ::: "memory")
#define CP_WAIT0()  asm volatile("cp.async.wait_group 0;" ::: "memory")

__device__ __forceinline__ uint32_t cvt_tf32(float v) {
    uint32_t t;
    asm("cvt.rna.tf32.f32 %0, %1;" : "=r"(t) : "f"(v));
    return t;
}

// D(16x8) += A(16x8,row) * B(8x8,col) ; tf32 inputs, f32 accum
__device__ __forceinline__ void mma8(float* c, const uint32_t* ar0, const uint32_t* ar1,
                                     const uint32_t* b) {
    asm volatile("mma.sync.aligned.m16n8k8.row.col.f32.tf32.tf32.f32 "
        "{%0,%1,%2,%3}, {%4,%5,%6,%7}, {%8,%9}, {%0,%1,%2,%3};"
        : "+f"(c[0]), "+f"(c[1]), "+f"(c[2]), "+f"(c[3])
        : "r"(ar0[0]), "r"(ar1[0]), "r"(ar0[1]), "r"(ar1[1]), "r"(b[0]), "r"(b[1]));
}

__device__ __forceinline__ unsigned long long pack2(float lo, float hi) {
    unsigned long long r;
    asm("mov.b64 %0, {%1, %2};" : "=l"(r) : "f"(lo), "f"(hi));
    return r;
}
__device__ __forceinline__ void unpack2(unsigned long long v, float& lo, float& hi) {
    asm("mov.b64 {%0, %1}, %2;" : "=f"(lo), "=f"(hi) : "l"(v));
}
__device__ __forceinline__ void fma2(unsigned long long& d, unsigned long long a, unsigned long long b) {
    asm("fma.rn.f32x2 %0, %1, %2, %3;" : "=l"(d) : "l"(a), "l"(b), "l"(d));
}

// accurate fast tanh: 1 - 2/(exp(2x)+1)  (abs err ~1e-7)
__device__ __forceinline__ float tanh_fast(float x) {
    float e;
    asm("ex2.approx.f32 %0, %1;" : "=f"(e) : "f"(x * 2.8853900817779268f));
    float r;
    asm("rcp.approx.f32 %0, %1;" : "=f"(r) : "f"(e + 1.0f));
    return fmaf(-2.0f, r, 1.0f);
}

// =====================================================================
// K0: g_wp = tf32_round(W + I), stored k-interleaved within each 32-chunk:
// linear index i = n*512 + kt*32 + k',  k' = (k&3)*8 + (k>>2)
// =====================================================================
__global__ void k0_prep(const float* __restrict__ fcw) {
    int i = blockIdx.x * 256 + threadIdx.x;
    if (i < 512 * 512) {
        int n = i >> 9, rem = i & 511;
        int kt = rem >> 5, kp = rem & 31;
        int k = kt * 32 + (kp >> 3) + (kp & 7) * 4;
        float v = fcw[n * 512 + k] + (n == k ? 1.0f : 0.0f);
        g_wp[i] = __uint_as_float(cvt_tf32(v));
    }
}

// =====================================================================
// K1: tf32 mma.sync GEMM (t = x@(W+I)^T + b) -> bilinear -> tanh -> s + BN partials
// grid = 1568, block = 256 (8 warps: 2 m x 4 n)
// =====================================================================
__global__ void __launch_bounds__(256, 1)
k1_gemm_bilinear(const float* __restrict__ x, const float* __restrict__ fcb)
{
    extern __shared__ char sm[];
    float* smf = (float*)sm;
    const uint32_t smb = smem_u32(sm);
    const int tid = threadIdx.x;
    const int lid = tid & 31;
    const int wid = tid >> 5;
    const int wm = wid >> 2;            // 0..1
    const int wn = wid & 3;             // 0..3
    const int cta = blockIdx.x;
    const int n0 = cta * BM;

    // bias -> smem (region disjoint from stage buffers)
    smf[BIAS_OFF / 4 + tid] = fcb[tid];
    smf[BIAS_OFF / 4 + 256 + tid] = fcb[256 + tid];

    // ---- A loader coords: thread owns (row ar, k residue klo), 8 cp4/stage ----
    const int klo = tid >> 6;           // 0..3
    const int ar = tid & 63;
    {
    }
    const int an = n0 + ar;
    const int ab_ = an / SPATIAL;
    const float* aptr = x + (size_t)ab_ * (512 * SPATIAL) + (an - ab_ * SPATIAL);
    const uint32_t adst = smb + (uint32_t)(ar * ASTRIDE + klo * 8) * 4;

    auto loadA = [&](int kt, uint32_t st) {
        #pragma unroll
        for (int j = 0; j < 8; ++j)
            cp4(adst + st + j * 4, aptr + (size_t)(kt * KC + klo + 4 * j) * SPATIAL);
    };
    auto loadB = [&](int kt, uint32_t st) {
        #pragma unroll
        for (int i = 0; i < 32; ++i) {
            int idx = i * 256 + tid;
            int n = idx >> 4, h = idx & 15;
            cp8(smb + st + ABYTES + (uint32_t)(n * BSTR + h * 2) * 4,
                g_wp + (size_t)n * 512 + kt * KC + h * 2);
        }
    };

    loadA(0, 0); loadB(0, 0); CP_COMMIT();
    loadA(1, STAGEB); loadB(1, STAGEB); CP_COMMIT();

    float acc[2][16][4];
    #pragma unroll
    for (int a = 0; a < 2; ++a)
        #pragma unroll
        for (int b = 0; b < 16; ++b)
            #pragma unroll
            for (int c = 0; c < 4; ++c) acc[a][b][c] = 0.0f;

    const int rbase = wm * 32 + (lid >> 2);     // A fragment rows: rbase + 8*i
    const int alo = (lid & 3) * 8;              // k' base within row

    for (int kt = 0; kt < NSTG; ++kt) {
        if (kt == NSTG - 1) { CP_WAIT0(); } else { CP_WAIT1(); }
        __syncthreads();
        const uint32_t stb = (kt & 1) * STAGEB;
        char* As = sm + stb;
        char* Bs = sm + stb + ABYTES;

        // A fragments for all 4 k-steps (tf32-rounded)
        uint32_t aa[4][4][2];
        #pragma unroll
        for (int i = 0; i < 4; ++i) {
            #pragma unroll
            for (int ks = 0; ks < 4; ++ks) {
                float2 v = *(const float2*)(As + ((rbase + 8 * i) * ASTRIDE + alo + 2 * ks) * 4);
                aa[i][ks][0] = cvt_tf32(v.x);
                aa[i][ks][1] = cvt_tf32(v.y);
            }
        }
        #pragma unroll
        for (int ks = 0; ks < 4; ++ks) {
            uint32_t bf[16][2];
            #pragma unroll
            for (int nt = 0; nt < 16; ++nt) {
                float2 bv = *(const float2*)(Bs +
                    ((wn * 128 + nt * 8 + (lid >> 2)) * BSTR + alo + 2 * ks) * 4);
                bf[nt][0] = __float_as_uint(bv.x);
                bf[nt][1] = __float_as_uint(bv.y);
            }
            #pragma unroll
            for (int nt = 0; nt < 16; ++nt) {
                mma8(acc[0][nt], aa[0][ks], aa[1][ks], bf[nt]);
                mma8(acc[1][nt], aa[2][ks], aa[3][ks], bf[nt]);
            }
        }
        __syncthreads();
        if (kt + 2 < NSTG) {
            loadA(kt + 2, stb);
            loadB(kt + 2, stb);
            CP_COMMIT();
        }
    }

    // ---- write t' (+bias) to smem staging [64][520] ----
    float* ts = smf;
    const float* bias = smf + BIAS_OFF / 4;
    #pragma unroll
    for (int mt = 0; mt < 2; ++mt) {
        const int r = wm * 32 + mt * 16 + (lid >> 2);
        #pragma unroll
        for (int nt = 0; nt < 16; ++nt) {
            const int n = wn * 128 + nt * 8 + (lid & 3) * 2;
            const float b0 = bias[n], b1 = bias[n + 1];
            *(float2*)(ts + r * TS_STRIDE + n) =
                make_float2(acc[mt][nt][0] + b0, acc[mt][nt][1] + b1);
            *(float2*)(ts + (r + 8) * TS_STRIDE + n) =
                make_float2(acc[mt][nt][2] + b0, acc[mt][nt][3] + b1);
        }
    }
    __syncthreads();

    // ---- bilinear: s[p][q] = tanh( (sum_g t[g*16+p]*t[g*16+q]) / 32 ) ----
    float* sst = smf + SST_OFF / 4;
    {
        const int r = tid >> 2;         // 0..63
        const int pp = tid & 3;
        const float* trow = ts + r * TS_STRIDE;
        unsigned long long sacc[4][8];
        #pragma unroll
        for (int h = 0; h < 4; ++h)
            #pragma unroll
            for (int e = 0; e < 8; ++e) sacc[h][e] = 0ull;
        for (int g = 0; g < 32; ++g) {
            F4U q0, q1, q2, q3;
            q0.v = *(const float4*)(trow + g * 16);
            q1.v = *(const float4*)(trow + g * 16 + 4);
            q2.v = *(const float4*)(trow + g * 16 + 8);
            q3.v = *(const float4*)(trow + g * 16 + 12);
            float tp0 = (pp == 0) ? q0.f[0] : (pp == 1) ? q0.f[1] : (pp == 2) ? q0.f[2] : q0.f[3];
            float tp1 = (pp == 0) ? q1.f[0] : (pp == 1) ? q1.f[1] : (pp == 2) ? q1.f[2] : q1.f[3];
            float tp2 = (pp == 0) ? q2.f[0] : (pp == 1) ? q2.f[1] : (pp == 2) ? q2.f[2] : q2.f[3];
            float tp3 = (pp == 0) ? q3.f[0] : (pp == 1) ? q3.f[1] : (pp == 2) ? q3.f[2] : q3.f[3];
            unsigned long long t0 = pack2(tp0, tp0), t1 = pack2(tp1, tp1);
            unsigned long long t2 = pack2(tp2, tp2), t3 = pack2(tp3, tp3);
            fma2(sacc[0][0], t0, q0.u[0]); fma2(sacc[0][1], t0, q0.u[1]);
            fma2(sacc[0][2], t0, q1.u[0]); fma2(sacc[0][3], t0, q1.u[1]);
            fma2(sacc[0][4], t0, q2.u[0]); fma2(sacc[0][5], t0, q2.u[1]);
            fma2(sacc[0][6], t0, q3.u[0]); fma2(sacc[0][7], t0, q3.u[1]);
            fma2(sacc[1][0], t1, q0.u[0]); fma2(sacc[1][1], t1, q0.u[1]);
            fma2(sacc[1][2], t1, q1.u[0]); fma2(sacc[1][3], t1, q1.u[1]);
            fma2(sacc[1][4], t1, q2.u[0]); fma2(sacc[1][5], t1, q2.u[1]);
            fma2(sacc[1][6], t1, q3.u[0]); fma2(sacc[1][7], t1, q3.u[1]);
            fma2(sacc[2][0], t2, q0.u[0]); fma2(sacc[2][1], t2, q0.u[1]);
            fma2(sacc[2][2], t2, q1.u[0]); fma2(sacc[2][3], t2, q1.u[1]);
            fma2(sacc[2][4], t2, q2.u[0]); fma2(sacc[2][5], t2, q2.u[1]);
            fma2(sacc[2][6], t2, q3.u[0]); fma2(sacc[2][7], t2, q3.u[1]);
            fma2(sacc[3][0], t3, q0.u[0]); fma2(sacc[3][1], t3, q0.u[1]);
            fma2(sacc[3][2], t3, q1.u[0]); fma2(sacc[3][3], t3, q1.u[1]);
            fma2(sacc[3][4], t3, q2.u[0]); fma2(sacc[3][5], t3, q2.u[1]);
            fma2(sacc[3][6], t3, q3.u[0]); fma2(sacc[3][7], t3, q3.u[1]);
        }
        #pragma unroll
        for (int h = 0; h < 4; ++h) {
            const int p = pp + 4 * h;
            #pragma unroll
            for (int e = 0; e < 8; ++e) {
                float lo, hi;
                unpack2(sacc[h][e], lo, hi);
                const int q = 2 * e;
                sst[(p * 16 + q) * SST_STR + r]     = tanh_fast(lo * 0.03125f);
                sst[(p * 16 + q + 1) * SST_STR + r] = tanh_fast(hi * 0.03125f);
            }
        }
    }
    __syncthreads();

    // ---- BN partials (thread = channel) ----
    {
        float s = 0.0f, q = 0.0f;
        const float* row = sst + tid * SST_STR;
        #pragma unroll
        for (int m4 = 0; m4 < 16; ++m4) {
            float4 v = *(const float4*)(row + m4 * 4);
            s += (v.x + v.y) + (v.z + v.w);
            q += fmaf(v.x, v.x, fmaf(v.y, v.y, fmaf(v.z, v.z, v.w * v.w)));
        }
        g_part[tid * NCTA + cta] = s;
        g_part[(tid + 256) * NCTA + cta] = q;
    }
    // ---- coalesced channel-major s write ----
    #pragma unroll
    for (int it = 0; it < 16; ++it) {
        int idx = it * 256 + tid;
        int ch = idx >> 4, f4 = idx & 15;
        float4 v = *(const float4*)(sst + ch * SST_STR + f4 * 4);
        *(float4*)(g_sT + (size_t)ch * TOTAL_N + n0 + f4 * 4) = v;
    }
}

// =====================================================================
// K2: fold BN stats -> per-channel scale/shift (fp64 reduction)
// =====================================================================
__global__ void k2_stats(const float* __restrict__ gamma,
                         const float* __restrict__ beta)
{
    __shared__ double rs[256], rq[256];
    const int c = blockIdx.x;
    const int c2 = c >> 1;
    const int tid = threadIdx.x;
    double s = 0.0, q = 0.0;
    for (int i = tid; i < NCTA; i += 256) {
        s += (double)g_part[c2 * NCTA + i];
        q += (double)g_part[(c2 + 256) * NCTA + i];
    }
    rs[tid] = s; rq[tid] = q;
    __syncthreads();
    for (int off = 128; off > 0; off >>= 1) {
        if (tid < off) { rs[tid] += rs[tid + off]; rq[tid] += rq[tid + off]; }
        __syncthreads();
    }
    if (tid == 0) {
        const double inv_n = 1.0 / (double)TOTAL_N;
        const double mean = rs[0] * inv_n;
        const double var = rq[0] * inv_n - mean * mean;
        const double rstd = 1.0 / sqrt(var + 1e-5);
        const double g = (double)gamma[c];
        g_scale[c] = (float)(g * rstd);
        g_shift[c] = (float)((double)beta[c] - mean * rstd * g);
    }
}

// =====================================================================
// K3: out = x + s[c>>1]*scale[c] + shift[c]   (float4)
// =====================================================================
__global__ void k3_out(const float* __restrict__ x, float* __restrict__ out)
{
    const int i4 = blockIdx.x * 256 + threadIdx.x;
    if (i4 >= TOTAL_OUT / 4) return;
    const int bc = i4 / 784;            // SPATIAL/4
    const int sp4 = i4 - bc * 784;
    const int c = bc & 511;
    const int b = bc >> 9;
    const float4 sv = *(const float4*)(g_sT + (size_t)(c >> 1) * TOTAL_N + b * SPATIAL + sp4 * 4);
    const float4 xv = *(const float4*)(x + (size_t)i4 * 4);
    const float sc = g_scale[c], sh = g_shift[c];
    float4 o;
    o.x = xv.x + fmaf(sv.x, sc, sh);
    o.y = xv.y + fmaf(sv.y, sc, sh);
    o.z = xv.z + fmaf(sv.z, sc, sh);
    o.w = xv.w + fmaf(sv.w, sc, sh);
    *(float4*)(out + (size_t)i4 * 4) = o;
}

// =====================================================================
extern "C" void kernel_launch(void* const* d_in, const int* in_sizes, int n_in,
                              void* d_out, int out_size)
{
    const float* x     = (const float*)d_in[0];
    const float* fcw   = (const float*)d_in[1];
    const float* fcb   = (const float*)d_in[2];
    const float* gamma = (const float*)d_in[3];
    const float* beta  = (const float*)d_in[4];
    float* out = (float*)d_out;

    cudaFuncSetAttribute(k1_gemm_bilinear,
                         cudaFuncAttributeMaxDynamicSharedMemorySize, SMEM_BYTES);

    k0_prep<<<1024, 256>>>(fcw);
    k1_gemm_bilinear<<<NCTA, 256, SMEM_BYTES>>>(x, fcb);
    k2_stats<<<512, 256>>>(gamma, beta);
    k3_out<<<(TOTAL_OUT / 4 + 255) / 256, 256>>>(x, out);
}

// round 4
// speedup vs baseline: 3.7504x; 1.6289x over previous
#include <cuda_runtime.h>
#include <cuda_fp16.h>
#include <cstdint>

// ---------------- problem constants ----------------
#define SPATIAL   3136
#define TOTAL_N   100352
#define BM        64
#define NCTA      1568                // TOTAL_N / BM
#define KC        32
#define NSTG      16                  // 512 / 32
#define ASTRIDE   40                  // padded floats per A smem row (conflict-free)
#define BSTRH     48                  // padded halves per B smem row (conflict-free)
#define ABYTES    (64 * ASTRIDE * 4)      // 10240
#define BBYTES    (512 * BSTRH * 2)       // 49152
#define STAGEB    (ABYTES + BBYTES)       // 59392
#define TS_STRIDE 520
#define SST_OFF   133120              // 64*520*4
#define SST_STR   68
#define BIAS_OFF  202752              // SST_OFF + 256*68*4
#define SMEM_BYTES 204800
#define TOTAL_OUT (32 * 512 * SPATIAL)

// ---------------- device scratch ----------------
__device__ __half g_wph[512 * 512];        // (W + I) fp16, k-interleaved per 16-chunk
__device__ __half g_sTh[256u * 100352u];   // s channel-major [256][N], fp16
__device__ float g_part[512 * NCTA];
__device__ float g_scale[512];
__device__ float g_shift[512];

// ---------------- helpers ----------------
union F4U { float4 v; unsigned long long u[2]; float f[4]; };

__device__ __forceinline__ uint32_t smem_u32(const void* p) {
    uint32_t a;
    asm("{ .reg .u64 t; cvta.to.shared.u64 t, %1; cvt.u32.u64 %0, t; }" : "=r"(a) : "l"(p));
    return a;
}
__device__ __forceinline__ void cp4(uint32_t dst, const void* src) {
    asm volatile("cp.async.ca.shared.global [%0], [%1], 4;" :: "r"(dst), "l"(src));
}
__device__ __forceinline__ void cp16(uint32_t dst, const void* src) {
    asm volatile("cp.async.cg.shared.global [%0], [%1], 16;" :: "r"(dst), "l"(src));
}
#define CP_COMMIT() asm volatile("cp.async.commit_group;" ::: "memory")
#define CP_WAIT1()  asm volatile("cp.async.wait_group 1;" ::: "memory")
#define CP_WAIT0()  asm volatile("cp.async.wait_group 0;" ::: "memory")

__device__ __forceinline__ uint32_t pack_f2h(float lo, float hi) {
    __half2 h = __floats2half2_rn(lo, hi);     // .x (low bits) = lo
    return *reinterpret_cast<uint32_t*>(&h);
}

// D(16x8) += A(16x16,row) * B(16x8,col) ; f16 inputs, f32 accum
__device__ __forceinline__ void mma16(float* c, const uint32_t* a, const uint32_t* b) {
    asm volatile("mma.sync.aligned.m16n8k16.row.col.f32.f16.f16.f32 "
        "{%0,%1,%2,%3}, {%4,%5,%6,%7}, {%8,%9}, {%0,%1,%2,%3};"
        : "+f"(c[0]), "+f"(c[1]), "+f"(c[2]), "+f"(c[3])
        : "r"(a[0]), "r"(a[1]), "r"(a[2]), "r"(a[3]), "r"(b[0]), "r"(b[1]));
}

__device__ __forceinline__ unsigned long long pack2(float lo, float hi) {
    unsigned long long r;
    asm("mov.b64 %0, {%1, %2};" : "=l"(r) : "f"(lo), "f"(hi));
    return r;
}
__device__ __forceinline__ void unpack2(unsigned long long v, float& lo, float& hi) {
    asm("mov.b64 {%0, %1}, %2;" : "=f"(lo), "=f"(hi) : "l"(v));
}
__device__ __forceinline__ void fma2(unsigned long long& d, unsigned long long a, unsigned long long b) {
    asm("fma.rn.f32x2 %0, %1, %2, %3;" : "=l"(d) : "l"(a), "l"(b), "l"(d));
}

// accurate fast tanh: 1 - 2/(exp(2x)+1)  (abs err ~1e-7)
__device__ __forceinline__ float tanh_fast(float x) {
    float e;
    asm("ex2.approx.f32 %0, %1;" : "=f"(e) : "f"(x * 2.8853900817779268f));
    float r;
    asm("rcp.approx.f32 %0, %1;" : "=f"(r) : "f"(e + 1.0f));
    return fmaf(-2.0f, r, 1.0f);
}

// =====================================================================
// K0: g_wph = fp16(W + I), k-interleaved within each k16 block:
// order [0,1,8,9, 2,3,10,11, 4,5,12,13, 6,7,14,15]
// =====================================================================
__global__ void k0_prep(const float* __restrict__ fcw) {
    int i = blockIdx.x * 256 + threadIdx.x;
    if (i < 512 * 512) {
        int n = i >> 9, k = i & 511;
        float v = fcw[i] + (n == k ? 1.0f : 0.0f);
        int kk = k & 15;
        int pos = (k & ~15) + ((kk & 7) >> 1) * 4 + (kk & 1) + (((kk >> 3) & 1) << 1);
        g_wph[n * 512 + pos] = __float2half_rn(v);
    }
}

// =====================================================================
// K1: fp16 mma.sync GEMM (t = x@(W+I)^T + b) -> bilinear -> tanh -> s + BN partials
// grid = 1568, block = 256 (8 warps: 2 m x 4 n)
// =====================================================================
__global__ void __launch_bounds__(256, 1)
k1_gemm_bilinear(const float* __restrict__ x, const float* __restrict__ fcb)
{
    extern __shared__ char sm[];
    float* smf = (float*)sm;
    const uint32_t smb = smem_u32(sm);
    const int tid = threadIdx.x;
    const int lid = tid & 31;
    const int wid = tid >> 5;
    const int wm = wid >> 2;            // 0..1
    const int wn = wid & 3;             // 0..3
    const int g  = lid >> 2;            // group id 0..7
    const int t4 = lid & 3;             // thread-in-group
    const int cta = blockIdx.x;
    const int n0 = cta * BM;

    // bias -> smem (region disjoint from stage buffers)
    smf[BIAS_OFF / 4 + tid] = fcb[tid];
    smf[BIAS_OFF / 4 + 256 + tid] = fcb[256 + tid];

    // ---- A loader coords ----
    const int klo = tid >> 6;           // 0..3
    const int ar = tid & 63;
    const int an = n0 + ar;
    const int ab_ = an / SPATIAL;
    const float* aptr = x + (size_t)ab_ * (512 * SPATIAL) + (an - ab_ * SPATIAL);

    auto loadA = [&](int kt, uint32_t st) {
        #pragma unroll
        for (int j = 0; j < 8; ++j)
            cp4(smb + st + (uint32_t)(ar * ASTRIDE + klo + 4 * j) * 4,
                aptr + (size_t)(kt * KC + klo + 4 * j) * SPATIAL);
    };
    auto loadB = [&](int kt, uint32_t st) {
        #pragma unroll
        for (int i = 0; i < 8; ++i) {
            int idx = i * 256 + tid;
            int n = idx >> 2, ch = idx & 3;
            cp16(smb + st + ABYTES + (uint32_t)(n * BSTRH * 2 + ch * 16),
                 g_wph + (size_t)n * 512 + kt * KC + ch * 8);
        }
    };

    loadA(0, 0); loadB(0, 0); CP_COMMIT();
    loadA(1, STAGEB); loadB(1, STAGEB); CP_COMMIT();

    float acc[2][16][4];
    #pragma unroll
    for (int a = 0; a < 2; ++a)
        #pragma unroll
        for (int b = 0; b < 16; ++b)
            #pragma unroll
            for (int c = 0; c < 4; ++c) acc[a][b][c] = 0.0f;

    for (int kt = 0; kt < NSTG; ++kt) {
        if (kt == NSTG - 1) { CP_WAIT0(); } else { CP_WAIT1(); }
        __syncthreads();
        const uint32_t stb = (kt & 1) * STAGEB;
        const float* As = (const float*)(sm + stb);
        const __half* Bs = (const __half*)(sm + stb + ABYTES);

        // A fragments (fp32 smem -> fp16 regs)
        uint32_t aa[2][2][4];
        #pragma unroll
        for (int mt = 0; mt < 2; ++mt) {
            const int r0 = wm * 32 + mt * 16 + g;
            #pragma unroll
            for (int ks = 0; ks < 2; ++ks) {
                const int c0 = ks * 16 + 2 * t4;
                float2 v00 = *(const float2*)(As + r0 * ASTRIDE + c0);
                float2 v10 = *(const float2*)(As + (r0 + 8) * ASTRIDE + c0);
                float2 v01 = *(const float2*)(As + r0 * ASTRIDE + c0 + 8);
                float2 v11 = *(const float2*)(As + (r0 + 8) * ASTRIDE + c0 + 8);
                aa[mt][ks][0] = pack_f2h(v00.x, v00.y);
                aa[mt][ks][1] = pack_f2h(v10.x, v10.y);
                aa[mt][ks][2] = pack_f2h(v01.x, v01.y);
                aa[mt][ks][3] = pack_f2h(v11.x, v11.y);
            }
        }
        #pragma unroll
        for (int ks = 0; ks < 2; ++ks) {
            uint32_t bf[16][2];
            #pragma unroll
            for (int nt = 0; nt < 16; ++nt) {
                uint2 bv = *(const uint2*)(Bs + (wn * 128 + nt * 8 + g) * BSTRH
                                              + ks * 16 + 4 * t4);
                bf[nt][0] = bv.x; bf[nt][1] = bv.y;
            }
            #pragma unroll
            for (int nt = 0; nt < 16; ++nt) {
                mma16(acc[0][nt], aa[0][ks], bf[nt]);
                mma16(acc[1][nt], aa[1][ks], bf[nt]);
            }
        }
        __syncthreads();
        if (kt + 2 < NSTG) {
            loadA(kt + 2, stb);
            loadB(kt + 2, stb);
            CP_COMMIT();
        }
    }

    // ---- write t' (+bias) to smem staging [64][520] ----
    float* ts = smf;
    const float* bias = smf + BIAS_OFF / 4;
    #pragma unroll
    for (int mt = 0; mt < 2; ++mt) {
        const int r = wm * 32 + mt * 16 + g;
        #pragma unroll
        for (int nt = 0; nt < 16; ++nt) {
            const int n = wn * 128 + nt * 8 + t4 * 2;
            const float b0 = bias[n], b1 = bias[n + 1];
            *(float2*)(ts + r * TS_STRIDE + n) =
                make_float2(acc[mt][nt][0] + b0, acc[mt][nt][1] + b1);
            *(float2*)(ts + (r + 8) * TS_STRIDE + n) =
                make_float2(acc[mt][nt][2] + b0, acc[mt][nt][3] + b1);
        }
    }
    __syncthreads();

    // ---- bilinear: s[p][q] = tanh( (sum_g t[g*16+p]*t[g*16+q]) / 32 ), fp16-rounded ----
    float* sst = smf + SST_OFF / 4;
    {
        const int r = tid >> 2;         // 0..63
        const int pp = tid & 3;
        const float* trow = ts + r * TS_STRIDE;
        unsigned long long sacc[4][8];
        #pragma unroll
        for (int h = 0; h < 4; ++h)
            #pragma unroll
            for (int e = 0; e < 8; ++e) sacc[h][e] = 0ull;
        for (int gg = 0; gg < 32; ++gg) {
            F4U q0, q1, q2, q3;
            q0.v = *(const float4*)(trow + gg * 16);
            q1.v = *(const float4*)(trow + gg * 16 + 4);
            q2.v = *(const float4*)(trow + gg * 16 + 8);
            q3.v = *(const float4*)(trow + gg * 16 + 12);
            float tp0 = (pp == 0) ? q0.f[0] : (pp == 1) ? q0.f[1] : (pp == 2) ? q0.f[2] : q0.f[3];
            float tp1 = (pp == 0) ? q1.f[0] : (pp == 1) ? q1.f[1] : (pp == 2) ? q1.f[2] : q1.f[3];
            float tp2 = (pp == 0) ? q2.f[0] : (pp == 1) ? q2.f[1] : (pp == 2) ? q2.f[2] : q2.f[3];
            float tp3 = (pp == 0) ? q3.f[0] : (pp == 1) ? q3.f[1] : (pp == 2) ? q3.f[2] : q3.f[3];
            unsigned long long t0 = pack2(tp0, tp0), t1 = pack2(tp1, tp1);
            unsigned long long t2 = pack2(tp2, tp2), t3 = pack2(tp3, tp3);
            fma2(sacc[0][0], t0, q0.u[0]); fma2(sacc[0][1], t0, q0.u[1]);
            fma2(sacc[0][2], t0, q1.u[0]); fma2(sacc[0][3], t0, q1.u[1]);
            fma2(sacc[0][4], t0, q2.u[0]); fma2(sacc[0][5], t0, q2.u[1]);
            fma2(sacc[0][6], t0, q3.u[0]); fma2(sacc[0][7], t0, q3.u[1]);
            fma2(sacc[1][0], t1, q0.u[0]); fma2(sacc[1][1], t1, q0.u[1]);
            fma2(sacc[1][2], t1, q1.u[0]); fma2(sacc[1][3], t1, q1.u[1]);
            fma2(sacc[1][4], t1, q2.u[0]); fma2(sacc[1][5], t1, q2.u[1]);
            fma2(sacc[1][6], t1, q3.u[0]); fma2(sacc[1][7], t1, q3.u[1]);
            fma2(sacc[2][0], t2, q0.u[0]); fma2(sacc[2][1], t2, q0.u[1]);
            fma2(sacc[2][2], t2, q1.u[0]); fma2(sacc[2][3], t2, q1.u[1]);
            fma2(sacc[2][4], t2, q2.u[0]); fma2(sacc[2][5], t2, q2.u[1]);
            fma2(sacc[2][6], t2, q3.u[0]); fma2(sacc[2][7], t2, q3.u[1]);
            fma2(sacc[3][0], t3, q0.u[0]); fma2(sacc[3][1], t3, q0.u[1]);
            fma2(sacc[3][2], t3, q1.u[0]); fma2(sacc[3][3], t3, q1.u[1]);
            fma2(sacc[3][4], t3, q2.u[0]); fma2(sacc[3][5], t3, q2.u[1]);
            fma2(sacc[3][6], t3, q3.u[0]); fma2(sacc[3][7], t3, q3.u[1]);
        }
        #pragma unroll
        for (int h = 0; h < 4; ++h) {
            const int p = pp + 4 * h;
            #pragma unroll
            for (int e = 0; e < 8; ++e) {
                float lo, hi;
                unpack2(sacc[h][e], lo, hi);
                const int q = 2 * e;
                // round through fp16 so BN stats match stored values exactly
                float vlo = __half2float(__float2half_rn(tanh_fast(lo * 0.03125f)));
                float vhi = __half2float(__float2half_rn(tanh_fast(hi * 0.03125f)));
                sst[(p * 16 + q) * SST_STR + r]     = vlo;
                sst[(p * 16 + q + 1) * SST_STR + r] = vhi;
            }
        }
    }
    __syncthreads();

    // ---- BN partials (thread = channel) ----
    {
        float s = 0.0f, q = 0.0f;
        const float* row = sst + tid * SST_STR;
        #pragma unroll
        for (int m4 = 0; m4 < 16; ++m4) {
            float4 v = *(const float4*)(row + m4 * 4);
            s += (v.x + v.y) + (v.z + v.w);
            q += fmaf(v.x, v.x, fmaf(v.y, v.y, fmaf(v.z, v.z, v.w * v.w)));
        }
        g_part[tid * NCTA + cta] = s;
        g_part[(tid + 256) * NCTA + cta] = q;
    }
    // ---- coalesced channel-major s write (fp16) ----
    #pragma unroll
    for (int it = 0; it < 16; ++it) {
        int idx = it * 256 + tid;
        int ch = idx >> 4, c4 = idx & 15;
        float4 v = *(const float4*)(sst + ch * SST_STR + c4 * 4);
        __half2 h0 = __floats2half2_rn(v.x, v.y);
        __half2 h1 = __floats2half2_rn(v.z, v.w);
        uint2 o;
        o.x = *reinterpret_cast<uint32_t*>(&h0);
        o.y = *reinterpret_cast<uint32_t*>(&h1);
        *(uint2*)(g_sTh + (size_t)ch * TOTAL_N + n0 + c4 * 4) = o;
    }
}

// =====================================================================
// K2: fold BN stats -> per-channel scale/shift (fp64 reduction)
// =====================================================================
__global__ void k2_stats(const float* __restrict__ gamma,
                         const float* __restrict__ beta)
{
    __shared__ double rs[256], rq[256];
    const int c = blockIdx.x;
    const int c2 = c >> 1;
    const int tid = threadIdx.x;
    double s = 0.0, q = 0.0;
    for (int i = tid; i < NCTA; i += 256) {
        s += (double)g_part[c2 * NCTA + i];
        q += (double)g_part[(c2 + 256) * NCTA + i];
    }
    rs[tid] = s; rq[tid] = q;
    __syncthreads();
    for (int off = 128; off > 0; off >>= 1) {
        if (tid < off) { rs[tid] += rs[tid + off]; rq[tid] += rq[tid + off]; }
        __syncthreads();
    }
    if (tid == 0) {
        const double inv_n = 1.0 / (double)TOTAL_N;
        const double mean = rs[0] * inv_n;
        const double var = rq[0] * inv_n - mean * mean;
        const double rstd = 1.0 / sqrt(var + 1e-5);
        const double gm = (double)gamma[c];
        g_scale[c] = (float)(gm * rstd);
        g_shift[c] = (float)((double)beta[c] - mean * rstd * gm);
    }
}

// =====================================================================
// K3: out = x + s[c>>1]*scale[c] + shift[c]   (float4 / half4)
// =====================================================================
__global__ void k3_out(const float* __restrict__ x, float* __restrict__ out)
{
    const int i4 = blockIdx.x * 256 + threadIdx.x;
    if (i4 >= TOTAL_OUT / 4) return;
    const int bc = i4 / 784;            // SPATIAL/4
    const int sp4 = i4 - bc * 784;
    const int c = bc & 511;
    const int b = bc >> 9;
    uint2 raw = *(const uint2*)(g_sTh + (size_t)(c >> 1) * TOTAL_N + b * SPATIAL + sp4 * 4);
    __half2 h0 = *reinterpret_cast<__half2*>(&raw.x);
    __half2 h1 = *reinterpret_cast<__half2*>(&raw.y);
    float2 f0 = __half22float2(h0);
    float2 f1 = __half22float2(h1);
    const float4 xv = *(const float4*)(x + (size_t)i4 * 4);
    const float sc = g_scale[c], sh = g_shift[c];
    float4 o;
    o.x = xv.x + fmaf(f0.x, sc, sh);
    o.y = xv.y + fmaf(f0.y, sc, sh);
    o.z = xv.z + fmaf(f1.x, sc, sh);
    o.w = xv.w + fmaf(f1.y, sc, sh);
    *(float4*)(out + (size_t)i4 * 4) = o;
}

// =====================================================================
extern "C" void kernel_launch(void* const* d_in, const int* in_sizes, int n_in,
                              void* d_out, int out_size)
{
    const float* x     = (const float*)d_in[0];
    const float* fcw   = (const float*)d_in[1];
    const float* fcb   = (const float*)d_in[2];
    const float* gamma = (const float*)d_in[3];
    const float* beta  = (const float*)d_in[4];
    float* out = (float*)d_out;

    cudaFuncSetAttribute(k1_gemm_bilinear,
                         cudaFuncAttributeMaxDynamicSharedMemorySize, SMEM_BYTES);

    k0_prep<<<1024, 256>>>(fcw);
    k1_gemm_bilinear<<<NCTA, 256, SMEM_BYTES>>>(x, fcb);
    k2_stats<<<512, 256>>>(gamma, beta);
    k3_out<<<(TOTAL_OUT / 4 + 255) / 256, 256>>>(x, out);
}